// round 1
// baseline (speedup 1.0000x reference)
#include <cuda_runtime.h>
#include <math.h>

#define BB    2
#define TT    2048
#define CC    2048
#define HH    16
#define DD    128
#define MM    (BB*TT)          // 4096 token rows

// ---- static device scratch (allocation-free) ----
__device__ float g_q[BB*HH*TT*DD];     // [B,H,T,D]
__device__ float g_k[BB*HH*TT*DD];
__device__ float g_v[BB*HH*TT*DD];
__device__ float g_attn[BB*TT*CC];     // [B,T,C]

// ============================================================
// GEMM: Y[m,n] = sum_k A[m,k] * W[n,k]   (A row-major, W row-major)
// 128x128x16 tile, 256 threads, 8x8 per thread.
// ============================================================
__global__ __launch_bounds__(256) void gemm_qkv_kernel(
    const float* __restrict__ x,
    const float* __restrict__ Wq,
    const float* __restrict__ Wk,
    const float* __restrict__ Wv)
{
    __shared__ float As[16][128];
    __shared__ float Bs[16][128];

    const int tid = threadIdx.x;
    const int tx = tid & 15;
    const int ty = tid >> 4;
    const int m0 = blockIdx.y * 128;
    const int n0 = blockIdx.x * 128;

    const float* W = (blockIdx.z == 0) ? Wq : (blockIdx.z == 1) ? Wk : Wv;
    float* dst = (blockIdx.z == 0) ? g_q : (blockIdx.z == 1) ? g_k : g_v;

    float acc[8][8];
#pragma unroll
    for (int i = 0; i < 8; i++)
#pragma unroll
        for (int j = 0; j < 8; j++) acc[i][j] = 0.f;

    for (int k0 = 0; k0 < CC; k0 += 16) {
#pragma unroll
        for (int it = 0; it < 2; it++) {
            int f   = tid + it * 256;       // 0..511  -> 512 float4s per operand
            int row = f >> 2;               // 0..127
            int kq  = (f & 3) << 2;         // 0,4,8,12
            float4 a = *(const float4*)&x[(size_t)(m0 + row) * CC + k0 + kq];
            As[kq + 0][row] = a.x; As[kq + 1][row] = a.y;
            As[kq + 2][row] = a.z; As[kq + 3][row] = a.w;
            float4 b = *(const float4*)&W[(size_t)(n0 + row) * CC + k0 + kq];
            Bs[kq + 0][row] = b.x; Bs[kq + 1][row] = b.y;
            Bs[kq + 2][row] = b.z; Bs[kq + 3][row] = b.w;
        }
        __syncthreads();
#pragma unroll
        for (int kk = 0; kk < 16; kk++) {
            float a[8], b[8];
            *(float4*)&a[0] = *(const float4*)&As[kk][ty * 8];
            *(float4*)&a[4] = *(const float4*)&As[kk][ty * 8 + 4];
            *(float4*)&b[0] = *(const float4*)&Bs[kk][tx * 8];
            *(float4*)&b[4] = *(const float4*)&Bs[kk][tx * 8 + 4];
#pragma unroll
            for (int i = 0; i < 8; i++)
#pragma unroll
                for (int j = 0; j < 8; j++)
                    acc[i][j] = fmaf(a[i], b[j], acc[i][j]);
        }
        __syncthreads();
    }

    // epilogue: write into [B,H,T,D]
#pragma unroll
    for (int i = 0; i < 8; i++) {
        int m = m0 + ty * 8 + i;
        int b = m >> 11;          // /T
        int t = m & 2047;
#pragma unroll
        for (int j = 0; j < 8; j++) {
            int n = n0 + tx * 8 + j;
            int h = n >> 7;       // /D
            int d = n & 127;
            dst[(((size_t)(b * HH + h)) * TT + t) * DD + d] = acc[i][j];
        }
    }
}

__global__ __launch_bounds__(256) void gemm_out_kernel(
    const float* __restrict__ Wo, float* __restrict__ out)
{
    __shared__ float As[16][128];
    __shared__ float Bs[16][128];

    const int tid = threadIdx.x;
    const int tx = tid & 15;
    const int ty = tid >> 4;
    const int m0 = blockIdx.y * 128;
    const int n0 = blockIdx.x * 128;

    float acc[8][8];
#pragma unroll
    for (int i = 0; i < 8; i++)
#pragma unroll
        for (int j = 0; j < 8; j++) acc[i][j] = 0.f;

    for (int k0 = 0; k0 < CC; k0 += 16) {
#pragma unroll
        for (int it = 0; it < 2; it++) {
            int f   = tid + it * 256;
            int row = f >> 2;
            int kq  = (f & 3) << 2;
            float4 a = *(const float4*)&g_attn[(size_t)(m0 + row) * CC + k0 + kq];
            As[kq + 0][row] = a.x; As[kq + 1][row] = a.y;
            As[kq + 2][row] = a.z; As[kq + 3][row] = a.w;
            float4 b = *(const float4*)&Wo[(size_t)(n0 + row) * CC + k0 + kq];
            Bs[kq + 0][row] = b.x; Bs[kq + 1][row] = b.y;
            Bs[kq + 2][row] = b.z; Bs[kq + 3][row] = b.w;
        }
        __syncthreads();
#pragma unroll
        for (int kk = 0; kk < 16; kk++) {
            float a[8], b[8];
            *(float4*)&a[0] = *(const float4*)&As[kk][ty * 8];
            *(float4*)&a[4] = *(const float4*)&As[kk][ty * 8 + 4];
            *(float4*)&b[0] = *(const float4*)&Bs[kk][tx * 8];
            *(float4*)&b[4] = *(const float4*)&Bs[kk][tx * 8 + 4];
#pragma unroll
            for (int i = 0; i < 8; i++)
#pragma unroll
                for (int j = 0; j < 8; j++)
                    acc[i][j] = fmaf(a[i], b[j], acc[i][j]);
        }
        __syncthreads();
    }

#pragma unroll
    for (int i = 0; i < 8; i++) {
        int m = m0 + ty * 8 + i;
#pragma unroll
        for (int j = 0; j < 8; j++) {
            int n = n0 + tx * 8 + j;
            out[(size_t)m * CC + n] = acc[i][j];
        }
    }
}

// ============================================================
// RoPE (in-place on g_q, g_k). thread i handles pair (i, i+64).
// ============================================================
__global__ __launch_bounds__(64) void rope_kernel()
{
    const int i  = threadIdx.x;         // 0..63
    const int t  = blockIdx.x;          // 0..T-1
    const int bh = blockIdx.y;          // 0..B*H-1
    const size_t base = ((size_t)bh * TT + t) * DD;

    float inv = powf(10000.0f, -(float)(2 * i) / 128.0f);
    float ang = (float)t * inv;
    float s, c;
    sincosf(ang, &s, &c);

    float x1 = g_q[base + i], x2 = g_q[base + i + 64];
    g_q[base + i]      = x1 * c - x2 * s;
    g_q[base + i + 64] = x2 * c + x1 * s;

    x1 = g_k[base + i]; x2 = g_k[base + i + 64];
    g_k[base + i]      = x1 * c - x2 * s;
    g_k[base + i + 64] = x2 * c + x1 * s;
}

// ============================================================
// Flash attention: BM=64 q rows per block, BN=64 key tile, D=128.
// 128 threads. Q/K stored d-major in smem, V row-major, P padded.
// ============================================================
#define ATTN_SMEM_FLOATS (8192 + 8192 + 8192 + 64*65 + 64 + 64)
#define ATTN_SMEM_BYTES  (ATTN_SMEM_FLOATS * 4)

__global__ __launch_bounds__(128) void attn_kernel()
{
    extern __shared__ float sm[];
    float* Qt = sm;                 // [128][64] d-major
    float* Kt = Qt + 8192;          // [128][64] d-major
    float* Vs = Kt + 8192;          // [64][128] row-major
    float* Ps = Vs + 8192;          // [64][65]
    float* rs = Ps + 64 * 65;       // [64] rescale
    float* li = rs + 64;            // [64] 1/l

    const int tid = threadIdx.x;
    const int tx = tid & 15;        // 16 col-groups
    const int ty = tid >> 4;        // 8 row-groups
    const int q0 = blockIdx.x * 64;
    const int bh = blockIdx.y;

    const float* Qg = g_q + (size_t)bh * TT * DD;
    const float* Kg = g_k + (size_t)bh * TT * DD;
    const float* Vg = g_v + (size_t)bh * TT * DD;

    // load Q tile transposed (d-major)
    for (int f = tid; f < 2048; f += 128) {
        int row = f >> 5;                 // 0..63
        int c4  = (f & 31) << 2;          // 0..124
        float4 q4 = *(const float4*)&Qg[(size_t)(q0 + row) * DD + c4];
        Qt[(c4 + 0) * 64 + row] = q4.x;
        Qt[(c4 + 1) * 64 + row] = q4.y;
        Qt[(c4 + 2) * 64 + row] = q4.z;
        Qt[(c4 + 3) * 64 + row] = q4.w;
    }

    float accO[8][8];
#pragma unroll
    for (int i = 0; i < 8; i++)
#pragma unroll
        for (int j = 0; j < 8; j++) accO[i][j] = 0.f;

    float mrow = -INFINITY, lrow = 0.f;
    const float scale = 0.088388347648318447f;   // 1/sqrt(128)

    const int ktiles = (q0 >> 6) + 1;
    for (int kt = 0; kt < ktiles; kt++) {
        const int k0 = kt << 6;
        __syncthreads();   // previous consumers of Kt/Vs/Ps done
        for (int f = tid; f < 2048; f += 128) {
            int row = f >> 5;
            int c4  = (f & 31) << 2;
            float4 k4 = *(const float4*)&Kg[(size_t)(k0 + row) * DD + c4];
            Kt[(c4 + 0) * 64 + row] = k4.x;
            Kt[(c4 + 1) * 64 + row] = k4.y;
            Kt[(c4 + 2) * 64 + row] = k4.z;
            Kt[(c4 + 3) * 64 + row] = k4.w;
            float4 v4 = *(const float4*)&Vg[(size_t)(k0 + row) * DD + c4];
            *(float4*)&Vs[row * 128 + c4] = v4;
        }
        __syncthreads();

        // S = Q K^T   (each thread: 8 rows x 4 cols)
        float s[8][4];
#pragma unroll
        for (int i = 0; i < 8; i++)
#pragma unroll
            for (int j = 0; j < 4; j++) s[i][j] = 0.f;

#pragma unroll 4
        for (int d = 0; d < 128; d++) {
            float qa[8], kb[4];
            *(float4*)&qa[0] = *(const float4*)&Qt[d * 64 + ty * 8];
            *(float4*)&qa[4] = *(const float4*)&Qt[d * 64 + ty * 8 + 4];
            *(float4*)&kb[0] = *(const float4*)&Kt[d * 64 + tx * 4];
#pragma unroll
            for (int i = 0; i < 8; i++)
#pragma unroll
                for (int j = 0; j < 4; j++)
                    s[i][j] = fmaf(qa[i], kb[j], s[i][j]);
        }

        // scale + causal mask -> Ps
#pragma unroll
        for (int i = 0; i < 8; i++) {
            int qr = q0 + ty * 8 + i;
#pragma unroll
            for (int j = 0; j < 4; j++) {
                int kc = k0 + tx * 4 + j;
                float v = s[i][j] * scale;
                if (kc > qr) v = -INFINITY;
                Ps[(ty * 8 + i) * 65 + tx * 4 + j] = v;
            }
        }
        __syncthreads();

        // online softmax: thread r owns row r (m,l in registers)
        if (tid < 64) {
            float* prow = &Ps[tid * 65];
            float mx = mrow;
#pragma unroll 8
            for (int k = 0; k < 64; k++) mx = fmaxf(mx, prow[k]);
            float r   = __expf(mrow - mx);
            float sum = lrow * r;
#pragma unroll 8
            for (int k = 0; k < 64; k++) {
                float p = __expf(prow[k] - mx);
                prow[k] = p;
                sum += p;
            }
            mrow = mx; lrow = sum;
            rs[tid] = r;
        }
        __syncthreads();

        // O = diag(r) O + P V
        float rfac[8];
#pragma unroll
        for (int i = 0; i < 8; i++) rfac[i] = rs[ty * 8 + i];
#pragma unroll
        for (int i = 0; i < 8; i++)
#pragma unroll
            for (int j = 0; j < 8; j++) accO[i][j] *= rfac[i];

#pragma unroll 2
        for (int k = 0; k < 64; k++) {
            float pa[8], vb[8];
#pragma unroll
            for (int i = 0; i < 8; i++) pa[i] = Ps[(ty * 8 + i) * 65 + k];
            *(float4*)&vb[0] = *(const float4*)&Vs[k * 128 + tx * 8];
            *(float4*)&vb[4] = *(const float4*)&Vs[k * 128 + tx * 8 + 4];
#pragma unroll
            for (int i = 0; i < 8; i++)
#pragma unroll
                for (int j = 0; j < 8; j++)
                    accO[i][j] = fmaf(pa[i], vb[j], accO[i][j]);
        }
    }

    if (tid < 64) li[tid] = 1.0f / lrow;
    __syncthreads();

    const int b = bh >> 4;   // /H
    const int h = bh & 15;
#pragma unroll
    for (int i = 0; i < 8; i++) {
        int t = q0 + ty * 8 + i;
        float inv = li[ty * 8 + i];
        float* dstrow = &g_attn[((size_t)(b * TT + t)) * CC + h * DD];
#pragma unroll
        for (int j = 0; j < 8; j++)
            dstrow[tx * 8 + j] = accO[i][j] * inv;
    }
}

// ============================================================
extern "C" void kernel_launch(void* const* d_in, const int* in_sizes, int n_in,
                              void* d_out, int out_size)
{
    const float* x  = (const float*)d_in[0];
    const float* Wq = (const float*)d_in[1];
    const float* Wk = (const float*)d_in[2];
    const float* Wv = (const float*)d_in[3];
    const float* Wo = (const float*)d_in[4];
    float* out = (float*)d_out;

    // 1) fused QKV projections -> [B,H,T,D]
    gemm_qkv_kernel<<<dim3(CC / 128, MM / 128, 3), 256>>>(x, Wq, Wk, Wv);

    // 2) RoPE on q,k
    rope_kernel<<<dim3(TT, BB * HH), 64>>>();

    // 3) causal flash attention -> g_attn [B,T,C]
    cudaFuncSetAttribute(attn_kernel, cudaFuncAttributeMaxDynamicSharedMemorySize,
                         ATTN_SMEM_BYTES);
    attn_kernel<<<dim3(TT / 64, BB * HH), 128, ATTN_SMEM_BYTES>>>();

    // 4) output projection
    gemm_out_kernel<<<dim3(CC / 128, MM / 128), 256>>>(Wo, out);
}

// round 3
// speedup vs baseline: 1.3795x; 1.3795x over previous
#include <cuda_runtime.h>
#include <cuda_bf16.h>
#include <math.h>
#include <stdint.h>

#define BB    2
#define TT    2048
#define CC    2048
#define HH    16
#define DD    128
#define MM    (BB*TT)          // 4096 token rows

#define KC    32               // K per chunk
#define NCHUNK (CC/KC)         // 64
#define LDS_PAD 36             // bf16 elems per row (32 + 4 pad)

// ---- static device scratch (allocation-free) ----
__device__ float g_q[BB*HH*TT*DD];     // [B,H,T,D]
__device__ float g_k[BB*HH*TT*DD];
__device__ float g_v[BB*HH*TT*DD];
__device__ float g_attn[BB*TT*CC];     // [B,T,C]

// ============================================================
// helpers
// ============================================================
__device__ __forceinline__ void mma_bf16(float* d, const uint32_t* a, const uint32_t* b) {
    asm volatile(
        "mma.sync.aligned.m16n8k16.row.col.f32.bf16.bf16.f32 "
        "{%0,%1,%2,%3}, {%4,%5,%6,%7}, {%8,%9}, {%0,%1,%2,%3};"
        : "+f"(d[0]), "+f"(d[1]), "+f"(d[2]), "+f"(d[3])
        : "r"(a[0]), "r"(a[1]), "r"(a[2]), "r"(a[3]), "r"(b[0]), "r"(b[1]));
}

__device__ __forceinline__ void split2(float a, float b, uint32_t& hi, uint32_t& lo) {
    __nv_bfloat16 ha = __float2bfloat16_rn(a);
    __nv_bfloat16 hb = __float2bfloat16_rn(b);
    float la = a - __bfloat162float(ha);
    float lb = b - __bfloat162float(hb);
    __nv_bfloat162 h; h.x = ha; h.y = hb;
    hi = *(uint32_t*)&h;
    __nv_bfloat162 l = __floats2bfloat162_rn(la, lb);
    lo = *(uint32_t*)&l;
}

// ============================================================
// bf16x3 tensor-core GEMM mainloop.
// acc[i][j][4] = (A[m0:m0+128,:] @ W[n0:n0+128,:]^T) tile, fp32.
// 256 threads = 8 warps (2 x 4). Warp tile 64x32. K-chunk 32.
// Smem: Ah/Al/Bh/Bl each [128][36] bf16 (pad kills conflicts).
// Register-prefetch of next chunk's global loads.
// ============================================================
__device__ __forceinline__ void mma_mainloop(
    const float* __restrict__ A, const float* __restrict__ W,
    int m0, int n0,
    uint32_t* Ah32, uint32_t* Al32, uint32_t* Bh32, uint32_t* Bl32,
    float acc[4][4][4])
{
    const int tid  = threadIdx.x;
    const int wid  = tid >> 5;
    const int lane = tid & 31;
    const int wm   = wid >> 2;       // 0..1
    const int wn   = wid & 3;        // 0..3
    const int g    = lane >> 2;      // 0..7
    const int kc   = lane & 3;       // 0..3

    // loader mapping: thread t -> row r = t>>1, col base (t&1)*16, 4 float4s
    const int lr = tid >> 1;
    const int lc = (tid & 1) * 16;
    const float* Arow = A + (size_t)(m0 + lr) * CC + lc;
    const float* Wrow = W + (size_t)(n0 + lr) * CC + lc;

    float4 pa[4], pb[4];
#pragma unroll
    for (int q = 0; q < 4; q++) {
        pa[q] = *(const float4*)(Arow + q * 4);
        pb[q] = *(const float4*)(Wrow + q * 4);
    }

    for (int ic = 0; ic < NCHUNK; ic++) {
        __syncthreads();   // previous chunk's mma consumers done
        // convert + store current chunk
        const int sbase = lr * (LDS_PAD / 2) + lc / 2;   // b32 index
#pragma unroll
        for (int q = 0; q < 4; q++) {
            uint32_t h0, l0, h1, l1;
            split2(pa[q].x, pa[q].y, h0, l0);
            split2(pa[q].z, pa[q].w, h1, l1);
            Ah32[sbase + q * 2 + 0] = h0; Ah32[sbase + q * 2 + 1] = h1;
            Al32[sbase + q * 2 + 0] = l0; Al32[sbase + q * 2 + 1] = l1;
            split2(pb[q].x, pb[q].y, h0, l0);
            split2(pb[q].z, pb[q].w, h1, l1);
            Bh32[sbase + q * 2 + 0] = h0; Bh32[sbase + q * 2 + 1] = h1;
            Bl32[sbase + q * 2 + 0] = l0; Bl32[sbase + q * 2 + 1] = l1;
        }
        __syncthreads();

        // prefetch next chunk while computing this one
        if (ic + 1 < NCHUNK) {
            const float* An = Arow + (ic + 1) * KC;
            const float* Wn = Wrow + (ic + 1) * KC;
#pragma unroll
            for (int q = 0; q < 4; q++) {
                pa[q] = *(const float4*)(An + q * 4);
                pb[q] = *(const float4*)(Wn + q * 4);
            }
        }

#pragma unroll
        for (int kk = 0; kk < 2; kk++) {
            const int cb = kk * 8 + kc;   // b32 col index within 18-wide row
            uint32_t ah[4][4], al[4][4];
#pragma unroll
            for (int i = 0; i < 4; i++) {
                int r = wm * 64 + i * 16 + g;
                ah[i][0] = Ah32[r * 18 + cb];
                ah[i][1] = Ah32[(r + 8) * 18 + cb];
                ah[i][2] = Ah32[r * 18 + cb + 4];
                ah[i][3] = Ah32[(r + 8) * 18 + cb + 4];
                al[i][0] = Al32[r * 18 + cb];
                al[i][1] = Al32[(r + 8) * 18 + cb];
                al[i][2] = Al32[r * 18 + cb + 4];
                al[i][3] = Al32[(r + 8) * 18 + cb + 4];
            }
            uint32_t bh[4][2], bl[4][2];
#pragma unroll
            for (int j = 0; j < 4; j++) {
                int n = wn * 32 + j * 8 + g;
                bh[j][0] = Bh32[n * 18 + cb];
                bh[j][1] = Bh32[n * 18 + cb + 4];
                bl[j][0] = Bl32[n * 18 + cb];
                bl[j][1] = Bl32[n * 18 + cb + 4];
            }
#pragma unroll
            for (int i = 0; i < 4; i++)
#pragma unroll
                for (int j = 0; j < 4; j++) {
                    mma_bf16(acc[i][j], ah[i], bh[j]);
                    mma_bf16(acc[i][j], ah[i], bl[j]);
                    mma_bf16(acc[i][j], al[i], bh[j]);
                }
        }
    }
}

// ============================================================
// QKV projection -> scatter to [B,H,T,D]
// ============================================================
__global__ __launch_bounds__(256) void mma_gemm_qkv(
    const float* __restrict__ x,
    const float* __restrict__ Wq,
    const float* __restrict__ Wk,
    const float* __restrict__ Wv)
{
    __shared__ __align__(16) uint16_t sAh[128 * LDS_PAD];
    __shared__ __align__(16) uint16_t sAl[128 * LDS_PAD];
    __shared__ __align__(16) uint16_t sBh[128 * LDS_PAD];
    __shared__ __align__(16) uint16_t sBl[128 * LDS_PAD];

    const float* W = (blockIdx.z == 0) ? Wq : (blockIdx.z == 1) ? Wk : Wv;
    float* dst = (blockIdx.z == 0) ? g_q : (blockIdx.z == 1) ? g_k : g_v;
    const int m0 = blockIdx.y * 128;
    const int n0 = blockIdx.x * 128;

    float acc[4][4][4];
#pragma unroll
    for (int i = 0; i < 4; i++)
#pragma unroll
        for (int j = 0; j < 4; j++)
#pragma unroll
            for (int r = 0; r < 4; r++) acc[i][j][r] = 0.f;

    mma_mainloop(x, W, m0, n0, (uint32_t*)sAh, (uint32_t*)sAl,
                 (uint32_t*)sBh, (uint32_t*)sBl, acc);

    const int tid = threadIdx.x, wid = tid >> 5, lane = tid & 31;
    const int wm = wid >> 2, wn = wid & 3, g = lane >> 2, kc = lane & 3;
    const int h = n0 >> 7;                  // tile N==D: one head per CTA col-tile
#pragma unroll
    for (int i = 0; i < 4; i++) {
        int m = m0 + wm * 64 + i * 16 + g;  // row (and +8)
        int b = m >> 11;
        int t = m & 2047;
        float* d0 = dst + (((size_t)(b * HH + h)) * TT + t) * DD;
        int m8 = m + 8;
        float* d1 = dst + (((size_t)((m8 >> 11) * HH + h)) * TT + (m8 & 2047)) * DD;
#pragma unroll
        for (int j = 0; j < 4; j++) {
            int c = wn * 32 + j * 8 + kc * 2;
            d0[c]     = acc[i][j][0];
            d0[c + 1] = acc[i][j][1];
            d1[c]     = acc[i][j][2];
            d1[c + 1] = acc[i][j][3];
        }
    }
}

// ============================================================
// Output projection: out = g_attn @ Wo^T (row-major out)
// ============================================================
__global__ __launch_bounds__(256) void mma_gemm_out(
    const float* __restrict__ Wo, float* __restrict__ out)
{
    __shared__ __align__(16) uint16_t sAh[128 * LDS_PAD];
    __shared__ __align__(16) uint16_t sAl[128 * LDS_PAD];
    __shared__ __align__(16) uint16_t sBh[128 * LDS_PAD];
    __shared__ __align__(16) uint16_t sBl[128 * LDS_PAD];

    const int m0 = blockIdx.y * 128;
    const int n0 = blockIdx.x * 128;

    float acc[4][4][4];
#pragma unroll
    for (int i = 0; i < 4; i++)
#pragma unroll
        for (int j = 0; j < 4; j++)
#pragma unroll
            for (int r = 0; r < 4; r++) acc[i][j][r] = 0.f;

    mma_mainloop(g_attn, Wo, m0, n0, (uint32_t*)sAh, (uint32_t*)sAl,
                 (uint32_t*)sBh, (uint32_t*)sBl, acc);

    const int tid = threadIdx.x, wid = tid >> 5, lane = tid & 31;
    const int wm = wid >> 2, wn = wid & 3, g = lane >> 2, kc = lane & 3;
#pragma unroll
    for (int i = 0; i < 4; i++) {
        int m = m0 + wm * 64 + i * 16 + g;
        float* d0 = out + (size_t)m * CC + n0;
        float* d1 = out + (size_t)(m + 8) * CC + n0;
#pragma unroll
        for (int j = 0; j < 4; j++) {
            int c = wn * 32 + j * 8 + kc * 2;
            d0[c]     = acc[i][j][0];
            d0[c + 1] = acc[i][j][1];
            d1[c]     = acc[i][j][2];
            d1[c + 1] = acc[i][j][3];
        }
    }
}

// ============================================================
// RoPE (in-place on g_q, g_k). thread i handles pair (i, i+64).
// ============================================================
__global__ __launch_bounds__(64) void rope_kernel()
{
    const int i  = threadIdx.x;         // 0..63
    const int t  = blockIdx.x;          // 0..T-1
    const int bh = blockIdx.y;          // 0..B*H-1
    const size_t base = ((size_t)bh * TT + t) * DD;

    float inv = powf(10000.0f, -(float)(2 * i) / 128.0f);
    float ang = (float)t * inv;
    float s, c;
    sincosf(ang, &s, &c);

    float x1 = g_q[base + i], x2 = g_q[base + i + 64];
    g_q[base + i]      = x1 * c - x2 * s;
    g_q[base + i + 64] = x2 * c + x1 * s;

    x1 = g_k[base + i]; x2 = g_k[base + i + 64];
    g_k[base + i]      = x1 * c - x2 * s;
    g_k[base + i + 64] = x2 * c + x1 * s;
}

// ============================================================
// Flash attention: BM=64 q rows per block, BN=64 key tile, D=128.
// 128 threads. fp32 SIMT (mma conversion next).
// ============================================================
#define ATTN_SMEM_FLOATS (8192 + 8192 + 8192 + 64*65 + 64 + 64)
#define ATTN_SMEM_BYTES  (ATTN_SMEM_FLOATS * 4)

__global__ __launch_bounds__(128) void attn_kernel()
{
    extern __shared__ float sm[];
    float* Qt = sm;                 // [128][64] d-major
    float* Kt = Qt + 8192;          // [128][64] d-major
    float* Vs = Kt + 8192;          // [64][128] row-major
    float* Ps = Vs + 8192;          // [64][65]
    float* rs = Ps + 64 * 65;       // [64] rescale
    float* li = rs + 64;            // [64] 1/l

    const int tid = threadIdx.x;
    const int tx = tid & 15;
    const int ty = tid >> 4;
    const int q0 = blockIdx.x * 64;
    const int bh = blockIdx.y;

    const float* Qg = g_q + (size_t)bh * TT * DD;
    const float* Kg = g_k + (size_t)bh * TT * DD;
    const float* Vg = g_v + (size_t)bh * TT * DD;

    for (int f = tid; f < 2048; f += 128) {
        int row = f >> 5;
        int c4  = (f & 31) << 2;
        float4 q4 = *(const float4*)&Qg[(size_t)(q0 + row) * DD + c4];
        Qt[(c4 + 0) * 64 + row] = q4.x;
        Qt[(c4 + 1) * 64 + row] = q4.y;
        Qt[(c4 + 2) * 64 + row] = q4.z;
        Qt[(c4 + 3) * 64 + row] = q4.w;
    }

    float accO[8][8];
#pragma unroll
    for (int i = 0; i < 8; i++)
#pragma unroll
        for (int j = 0; j < 8; j++) accO[i][j] = 0.f;

    float mrow = -INFINITY, lrow = 0.f;
    const float scale = 0.088388347648318447f;

    const int ktiles = (q0 >> 6) + 1;
    for (int kt = 0; kt < ktiles; kt++) {
        const int k0 = kt << 6;
        __syncthreads();
        for (int f = tid; f < 2048; f += 128) {
            int row = f >> 5;
            int c4  = (f & 31) << 2;
            float4 k4 = *(const float4*)&Kg[(size_t)(k0 + row) * DD + c4];
            Kt[(c4 + 0) * 64 + row] = k4.x;
            Kt[(c4 + 1) * 64 + row] = k4.y;
            Kt[(c4 + 2) * 64 + row] = k4.z;
            Kt[(c4 + 3) * 64 + row] = k4.w;
            float4 v4 = *(const float4*)&Vg[(size_t)(k0 + row) * DD + c4];
            *(float4*)&Vs[row * 128 + c4] = v4;
        }
        __syncthreads();

        float s[8][4];
#pragma unroll
        for (int i = 0; i < 8; i++)
#pragma unroll
            for (int j = 0; j < 4; j++) s[i][j] = 0.f;

#pragma unroll 4
        for (int d = 0; d < 128; d++) {
            float qa[8], kb[4];
            *(float4*)&qa[0] = *(const float4*)&Qt[d * 64 + ty * 8];
            *(float4*)&qa[4] = *(const float4*)&Qt[d * 64 + ty * 8 + 4];
            *(float4*)&kb[0] = *(const float4*)&Kt[d * 64 + tx * 4];
#pragma unroll
            for (int i = 0; i < 8; i++)
#pragma unroll
                for (int j = 0; j < 4; j++)
                    s[i][j] = fmaf(qa[i], kb[j], s[i][j]);
        }

#pragma unroll
        for (int i = 0; i < 8; i++) {
            int qr = q0 + ty * 8 + i;
#pragma unroll
            for (int j = 0; j < 4; j++) {
                int kc = k0 + tx * 4 + j;
                float v = s[i][j] * scale;
                if (kc > qr) v = -INFINITY;
                Ps[(ty * 8 + i) * 65 + tx * 4 + j] = v;
            }
        }
        __syncthreads();

        if (tid < 64) {
            float* prow = &Ps[tid * 65];
            float mx = mrow;
#pragma unroll 8
            for (int k = 0; k < 64; k++) mx = fmaxf(mx, prow[k]);
            float r   = __expf(mrow - mx);
            float sum = lrow * r;
#pragma unroll 8
            for (int k = 0; k < 64; k++) {
                float p = __expf(prow[k] - mx);
                prow[k] = p;
                sum += p;
            }
            mrow = mx; lrow = sum;
            rs[tid] = r;
        }
        __syncthreads();

        float rfac[8];
#pragma unroll
        for (int i = 0; i < 8; i++) rfac[i] = rs[ty * 8 + i];
#pragma unroll
        for (int i = 0; i < 8; i++)
#pragma unroll
            for (int j = 0; j < 8; j++) accO[i][j] *= rfac[i];

#pragma unroll 2
        for (int k = 0; k < 64; k++) {
            float pa[8], vb[8];
#pragma unroll
            for (int i = 0; i < 8; i++) pa[i] = Ps[(ty * 8 + i) * 65 + k];
            *(float4*)&vb[0] = *(const float4*)&Vs[k * 128 + tx * 8];
            *(float4*)&vb[4] = *(const float4*)&Vs[k * 128 + tx * 8 + 4];
#pragma unroll
            for (int i = 0; i < 8; i++)
#pragma unroll
                for (int j = 0; j < 8; j++)
                    accO[i][j] = fmaf(pa[i], vb[j], accO[i][j]);
        }
    }

    if (tid < 64) li[tid] = 1.0f / lrow;
    __syncthreads();

    const int b = bh >> 4;
    const int h = bh & 15;
#pragma unroll
    for (int i = 0; i < 8; i++) {
        int t = q0 + ty * 8 + i;
        float inv = li[ty * 8 + i];
        float* dstrow = &g_attn[((size_t)(b * TT + t)) * CC + h * DD];
#pragma unroll
        for (int j = 0; j < 8; j++)
            dstrow[tx * 8 + j] = accO[i][j] * inv;
    }
}

// ============================================================
extern "C" void kernel_launch(void* const* d_in, const int* in_sizes, int n_in,
                              void* d_out, int out_size)
{
    const float* x  = (const float*)d_in[0];
    const float* Wq = (const float*)d_in[1];
    const float* Wk = (const float*)d_in[2];
    const float* Wv = (const float*)d_in[3];
    const float* Wo = (const float*)d_in[4];
    float* out = (float*)d_out;

    cudaFuncSetAttribute(attn_kernel, cudaFuncAttributeMaxDynamicSharedMemorySize,
                         ATTN_SMEM_BYTES);

    // 1) fused QKV projections (bf16x3 tensor cores) -> [B,H,T,D]
    mma_gemm_qkv<<<dim3(CC / 128, MM / 128, 3), 256>>>(x, Wq, Wk, Wv);

    // 2) RoPE on q,k
    rope_kernel<<<dim3(TT, BB * HH), 64>>>();

    // 3) causal flash attention -> g_attn [B,T,C]
    attn_kernel<<<dim3(TT / 64, BB * HH), 128, ATTN_SMEM_BYTES>>>();

    // 4) output projection (bf16x3 tensor cores)
    mma_gemm_out<<<dim3(CC / 128, MM / 128), 256>>>(Wo, out);
}

// round 5
// speedup vs baseline: 2.3472x; 1.7015x over previous
#include <cuda_runtime.h>
#include <cuda_bf16.h>
#include <math.h>
#include <stdint.h>

#define BB    2
#define TT    2048
#define CC    2048
#define HH    16
#define DD    128
#define MM    (BB*TT)          // 4096 token rows
#define BH    (BB*HH)          // 32

#define KC    32               // GEMM K per chunk
#define NCHUNK (CC/KC)         // 64

// ---- static device scratch (allocation-free) ----
__device__ float g_q[BH*TT*DD];        // fp32 [B,H,T,D]
__device__ float g_k[BH*TT*DD];
__device__ float g_v[BH*TT*DD];

__device__ __nv_bfloat16 g_xh[MM*CC],  g_xl[MM*CC];     // pre-split input
__device__ __nv_bfloat16 g_wqh[CC*CC], g_wql[CC*CC];
__device__ __nv_bfloat16 g_wkh[CC*CC], g_wkl[CC*CC];
__device__ __nv_bfloat16 g_wvh[CC*CC], g_wvl[CC*CC];
__device__ __nv_bfloat16 g_woh[CC*CC], g_wol[CC*CC];
__device__ __nv_bfloat16 g_qh[BH*TT*DD], g_ql[BH*TT*DD];   // roped q  [bh][t][d]
__device__ __nv_bfloat16 g_kh[BH*TT*DD], g_kl[BH*TT*DD];   // roped k  [bh][t][d]
__device__ __nv_bfloat16 g_vth[BH*DD*TT], g_vtl[BH*DD*TT]; // v transposed [bh][d][t]
__device__ __nv_bfloat16 g_ah[MM*CC],  g_al[MM*CC];        // attn out rows [B,T,C]

// ============================================================
// helpers
// ============================================================
__device__ __forceinline__ void mma_bf16(float* d, const uint32_t* a, const uint32_t* b) {
    asm volatile(
        "mma.sync.aligned.m16n8k16.row.col.f32.bf16.bf16.f32 "
        "{%0,%1,%2,%3}, {%4,%5,%6,%7}, {%8,%9}, {%0,%1,%2,%3};"
        : "+f"(d[0]), "+f"(d[1]), "+f"(d[2]), "+f"(d[3])
        : "r"(a[0]), "r"(a[1]), "r"(a[2]), "r"(a[3]), "r"(b[0]), "r"(b[1]));
}

__device__ __forceinline__ void split2(float a, float b, uint32_t& hi, uint32_t& lo) {
    __nv_bfloat16 ha = __float2bfloat16_rn(a);
    __nv_bfloat16 hb = __float2bfloat16_rn(b);
    float la = a - __bfloat162float(ha);
    float lb = b - __bfloat162float(hb);
    __nv_bfloat162 h; h.x = ha; h.y = hb;
    hi = *(uint32_t*)&h;
    __nv_bfloat162 l = __floats2bfloat162_rn(la, lb);
    lo = *(uint32_t*)&l;
}

// ============================================================
// one-shot fp32 -> bf16 hi/lo splitter
// ============================================================
__global__ __launch_bounds__(256) void split_one(const float* __restrict__ src, int which, int n4)
{
    int i = blockIdx.x * 256 + threadIdx.x;
    if (i >= n4) return;
    __nv_bfloat16 *h, *l;
    switch (which) {
        case 0:  h = g_xh;  l = g_xl;  break;
        case 1:  h = g_wqh; l = g_wql; break;
        case 2:  h = g_wkh; l = g_wkl; break;
        case 3:  h = g_wvh; l = g_wvl; break;
        default: h = g_woh; l = g_wol; break;
    }
    float4 v = ((const float4*)src)[i];
    uint32_t h0, l0, h1, l1;
    split2(v.x, v.y, h0, l0);
    split2(v.z, v.w, h1, l1);
    uint2 hh; hh.x = h0; hh.y = h1;
    uint2 ll; ll.x = l0; ll.y = l1;
    ((uint2*)h)[i] = hh;
    ((uint2*)l)[i] = ll;
}

// ============================================================
// bf16x3 GEMM mainloop (pre-split inputs).
// 256 threads = 8 warps (2x4), warp tile 64x32, K chunk 32.
// Smem [128][40] bf16 per array (stride 20 b32, conflict-free frags).
// ============================================================
struct GemmSmem {
    __nv_bfloat16 Ah[128 * 40];
    __nv_bfloat16 Al[128 * 40];
    __nv_bfloat16 Bh[128 * 40];
    __nv_bfloat16 Bl[128 * 40];
};

__device__ __forceinline__ void mma_mainloop2(
    const __nv_bfloat16* __restrict__ Ahg, const __nv_bfloat16* __restrict__ Alg,
    const __nv_bfloat16* __restrict__ Bhg, const __nv_bfloat16* __restrict__ Blg,
    int m0, int n0, GemmSmem* S, float acc[4][4][4])
{
    const int tid  = threadIdx.x;
    const int wid  = tid >> 5;
    const int lane = tid & 31;
    const int wm   = wid >> 2;
    const int wn   = wid & 3;
    const int g    = lane >> 2;
    const int kc   = lane & 3;

    uint32_t* sAh = (uint32_t*)S->Ah;
    uint32_t* sAl = (uint32_t*)S->Al;
    uint32_t* sBh = (uint32_t*)S->Bh;
    uint32_t* sBl = (uint32_t*)S->Bl;

    uint4 pah[2], pal[2], pbh[2], pbl[2];
#pragma unroll
    for (int it = 0; it < 2; it++) {
        int f = tid + it * 256;
        int row = f >> 2, seg = (f & 3) * 8;
        pah[it] = *(const uint4*)&Ahg[(size_t)(m0 + row) * CC + seg];
        pal[it] = *(const uint4*)&Alg[(size_t)(m0 + row) * CC + seg];
        pbh[it] = *(const uint4*)&Bhg[(size_t)(n0 + row) * CC + seg];
        pbl[it] = *(const uint4*)&Blg[(size_t)(n0 + row) * CC + seg];
    }

    for (int ic = 0; ic < NCHUNK; ic++) {
        __syncthreads();
#pragma unroll
        for (int it = 0; it < 2; it++) {
            int f = tid + it * 256;
            int row = f >> 2, seg = (f & 3) * 8;
            *(uint4*)((__nv_bfloat16*)S->Ah + row * 40 + seg) = pah[it];
            *(uint4*)((__nv_bfloat16*)S->Al + row * 40 + seg) = pal[it];
            *(uint4*)((__nv_bfloat16*)S->Bh + row * 40 + seg) = pbh[it];
            *(uint4*)((__nv_bfloat16*)S->Bl + row * 40 + seg) = pbl[it];
        }
        __syncthreads();
        if (ic + 1 < NCHUNK) {
            int k0 = (ic + 1) * KC;
#pragma unroll
            for (int it = 0; it < 2; it++) {
                int f = tid + it * 256;
                int row = f >> 2, seg = (f & 3) * 8;
                pah[it] = *(const uint4*)&Ahg[(size_t)(m0 + row) * CC + k0 + seg];
                pal[it] = *(const uint4*)&Alg[(size_t)(m0 + row) * CC + k0 + seg];
                pbh[it] = *(const uint4*)&Bhg[(size_t)(n0 + row) * CC + k0 + seg];
                pbl[it] = *(const uint4*)&Blg[(size_t)(n0 + row) * CC + k0 + seg];
            }
        }
#pragma unroll
        for (int kk = 0; kk < 2; kk++) {
            const int cb = kk * 8 + kc;
            uint32_t ah[4][4], al[4][4];
#pragma unroll
            for (int i = 0; i < 4; i++) {
                int r = wm * 64 + i * 16 + g;
                ah[i][0] = sAh[r * 20 + cb];
                ah[i][1] = sAh[(r + 8) * 20 + cb];
                ah[i][2] = sAh[r * 20 + cb + 4];
                ah[i][3] = sAh[(r + 8) * 20 + cb + 4];
                al[i][0] = sAl[r * 20 + cb];
                al[i][1] = sAl[(r + 8) * 20 + cb];
                al[i][2] = sAl[r * 20 + cb + 4];
                al[i][3] = sAl[(r + 8) * 20 + cb + 4];
            }
            uint32_t bh[4][2], bl[4][2];
#pragma unroll
            for (int j = 0; j < 4; j++) {
                int n = wn * 32 + j * 8 + g;
                bh[j][0] = sBh[n * 20 + cb];
                bh[j][1] = sBh[n * 20 + cb + 4];
                bl[j][0] = sBl[n * 20 + cb];
                bl[j][1] = sBl[n * 20 + cb + 4];
            }
#pragma unroll
            for (int i = 0; i < 4; i++)
#pragma unroll
                for (int j = 0; j < 4; j++) {
                    mma_bf16(acc[i][j], ah[i], bh[j]);
                    mma_bf16(acc[i][j], ah[i], bl[j]);
                    mma_bf16(acc[i][j], al[i], bh[j]);
                }
        }
    }
}

// ============================================================
// QKV projection -> scatter fp32 to [B,H,T,D]
// ============================================================
__global__ __launch_bounds__(256) void mma_gemm_qkv()
{
    __shared__ GemmSmem S;
    const int z = blockIdx.z;
    const __nv_bfloat16* Bhg = (z == 0) ? g_wqh : (z == 1) ? g_wkh : g_wvh;
    const __nv_bfloat16* Blg = (z == 0) ? g_wql : (z == 1) ? g_wkl : g_wvl;
    float* dst = (z == 0) ? g_q : (z == 1) ? g_k : g_v;
    const int m0 = blockIdx.y * 128;
    const int n0 = blockIdx.x * 128;

    float acc[4][4][4];
#pragma unroll
    for (int i = 0; i < 4; i++)
#pragma unroll
        for (int j = 0; j < 4; j++)
#pragma unroll
            for (int r = 0; r < 4; r++) acc[i][j][r] = 0.f;

    mma_mainloop2(g_xh, g_xl, Bhg, Blg, m0, n0, &S, acc);

    const int tid = threadIdx.x, wid = tid >> 5, lane = tid & 31;
    const int wm = wid >> 2, wn = wid & 3, g = lane >> 2, kc = lane & 3;
    const int h = n0 >> 7;
#pragma unroll
    for (int i = 0; i < 4; i++) {
        int m = m0 + wm * 64 + i * 16 + g;
        int b = m >> 11;
        int t = m & 2047;
        float* d0 = dst + (((size_t)(b * HH + h)) * TT + t) * DD;
        int m8 = m + 8;
        float* d1 = dst + (((size_t)((m8 >> 11) * HH + h)) * TT + (m8 & 2047)) * DD;
#pragma unroll
        for (int j = 0; j < 4; j++) {
            int c = wn * 32 + j * 8 + kc * 2;
            d0[c]     = acc[i][j][0];
            d0[c + 1] = acc[i][j][1];
            d1[c]     = acc[i][j][2];
            d1[c + 1] = acc[i][j][3];
        }
    }
}

// ============================================================
// Output projection: out = attn(hi/lo) @ Wo^T -> fp32
// ============================================================
__global__ __launch_bounds__(256) void mma_gemm_out(float* __restrict__ out)
{
    __shared__ GemmSmem S;
    const int m0 = blockIdx.y * 128;
    const int n0 = blockIdx.x * 128;

    float acc[4][4][4];
#pragma unroll
    for (int i = 0; i < 4; i++)
#pragma unroll
        for (int j = 0; j < 4; j++)
#pragma unroll
            for (int r = 0; r < 4; r++) acc[i][j][r] = 0.f;

    mma_mainloop2(g_ah, g_al, g_woh, g_wol, m0, n0, &S, acc);

    const int tid = threadIdx.x, wid = tid >> 5, lane = tid & 31;
    const int wm = wid >> 2, wn = wid & 3, g = lane >> 2, kc = lane & 3;
#pragma unroll
    for (int i = 0; i < 4; i++) {
        int m = m0 + wm * 64 + i * 16 + g;
        float* d0 = out + (size_t)m * CC + n0;
        float* d1 = out + (size_t)(m + 8) * CC + n0;
#pragma unroll
        for (int j = 0; j < 4; j++) {
            int c = wn * 32 + j * 8 + kc * 2;
            d0[c]     = acc[i][j][0];
            d0[c + 1] = acc[i][j][1];
            d1[c]     = acc[i][j][2];
            d1[c + 1] = acc[i][j][3];
        }
    }
}

// ============================================================
// RoPE + split: fp32 g_q/g_k -> bf16 hi/lo g_qh/g_ql/g_kh/g_kl
// ============================================================
__global__ __launch_bounds__(64) void rope_split_kernel()
{
    const int i  = threadIdx.x;
    const int t  = blockIdx.x;
    const int bh = blockIdx.y;
    const size_t base = ((size_t)bh * TT + t) * DD;

    float inv = powf(10000.0f, -(float)(2 * i) / 128.0f);
    float ang = (float)t * inv;
    float s_, c_;
    sincosf(ang, &s_, &c_);

    {
        float x1 = g_q[base + i], x2 = g_q[base + i + 64];
        float v1 = x1 * c_ - x2 * s_;
        float v2 = x2 * c_ + x1 * s_;
        __nv_bfloat16 h1 = __float2bfloat16_rn(v1);
        __nv_bfloat16 h2 = __float2bfloat16_rn(v2);
        g_qh[base + i]      = h1;
        g_ql[base + i]      = __float2bfloat16_rn(v1 - __bfloat162float(h1));
        g_qh[base + i + 64] = h2;
        g_ql[base + i + 64] = __float2bfloat16_rn(v2 - __bfloat162float(h2));
    }
    {
        float x1 = g_k[base + i], x2 = g_k[base + i + 64];
        float v1 = x1 * c_ - x2 * s_;
        float v2 = x2 * c_ + x1 * s_;
        __nv_bfloat16 h1 = __float2bfloat16_rn(v1);
        __nv_bfloat16 h2 = __float2bfloat16_rn(v2);
        g_kh[base + i]      = h1;
        g_kl[base + i]      = __float2bfloat16_rn(v1 - __bfloat162float(h1));
        g_kh[base + i + 64] = h2;
        g_kl[base + i + 64] = __float2bfloat16_rn(v2 - __bfloat162float(h2));
    }
}

// ============================================================
// V transpose + split: fp32 g_v [bh][t][d] -> bf16 hi/lo [bh][d][t]
// ============================================================
__global__ __launch_bounds__(256) void vsplit_transpose()
{
    __shared__ float tile[32][33];
    const int bh = blockIdx.z;
    const int t0 = blockIdx.x * 32;
    const int d0 = blockIdx.y * 32;
    const int tx = threadIdx.x & 31;
    const int ty = threadIdx.x >> 5;      // 0..7
    const float* src = g_v + (size_t)bh * TT * DD;
#pragma unroll
    for (int r = 0; r < 4; r++)
        tile[ty + r * 8][tx] = src[(size_t)(t0 + ty + r * 8) * DD + d0 + tx];
    __syncthreads();
    __nv_bfloat16* dh = g_vth + (size_t)bh * DD * TT;
    __nv_bfloat16* dl = g_vtl + (size_t)bh * DD * TT;
#pragma unroll
    for (int r = 0; r < 4; r++) {
        int d = d0 + ty + r * 8;
        float v = tile[tx][ty + r * 8];
        __nv_bfloat16 h = __float2bfloat16_rn(v);
        dh[(size_t)d * TT + t0 + tx] = h;
        dl[(size_t)d * TT + t0 + tx] = __float2bfloat16_rn(v - __bfloat162float(h));
    }
}

// ============================================================
// Tensor-core flash attention.
// BM=128 (8 warps x 16 rows), BN=64, D=128, bf16x3 QK and PV.
// ============================================================
#define AQH 0
#define AQL 17408
#define AKH 34816
#define AKL 43520
#define AVH 52224
#define AVL 61440
#define ATT_SMEM_BF16 70656
#define ATT_SMEM_BYTES (ATT_SMEM_BF16 * 2)

__global__ __launch_bounds__(256) void attn_mma_kernel()
{
    extern __shared__ __nv_bfloat16 sm[];
    __nv_bfloat16* sQh = sm + AQH;   // [128][136]
    __nv_bfloat16* sQl = sm + AQL;
    __nv_bfloat16* sKh = sm + AKH;   // [64][136]
    __nv_bfloat16* sKl = sm + AKL;
    __nv_bfloat16* sVh = sm + AVH;   // [128][72]  (d-major)
    __nv_bfloat16* sVl = sm + AVL;

    const int tid = threadIdx.x;
    const int wid = tid >> 5;
    const int lane = tid & 31;
    const int g  = lane >> 2;
    const int kc = lane & 3;
    const int bh = blockIdx.y;
    const int qt = gridDim.x - 1 - blockIdx.x;   // big tiles first
    const int q0 = qt * 128;

    const __nv_bfloat16* Qhg = g_qh + ((size_t)bh * TT + q0) * DD;
    const __nv_bfloat16* Qlg = g_ql + ((size_t)bh * TT + q0) * DD;
    const __nv_bfloat16* Khg = g_kh + (size_t)bh * TT * DD;
    const __nv_bfloat16* Klg = g_kl + (size_t)bh * TT * DD;
    const __nv_bfloat16* Vhg = g_vth + (size_t)bh * DD * TT;
    const __nv_bfloat16* Vlg = g_vtl + (size_t)bh * DD * TT;

    // load Q tile (128 x 128)
    for (int f = tid; f < 2048; f += 256) {
        int row = f >> 4, seg = (f & 15) * 8;
        *(uint4*)&sQh[row * 136 + seg] = *(const uint4*)&Qhg[row * DD + seg];
        *(uint4*)&sQl[row * 136 + seg] = *(const uint4*)&Qlg[row * DD + seg];
    }

    const uint32_t* q32h = (const uint32_t*)sQh;
    const uint32_t* q32l = (const uint32_t*)sQl;
    const uint32_t* k32h = (const uint32_t*)sKh;
    const uint32_t* k32l = (const uint32_t*)sKl;
    const uint32_t* v32h = (const uint32_t*)sVh;
    const uint32_t* v32l = (const uint32_t*)sVl;

    float o[16][4];
#pragma unroll
    for (int n = 0; n < 16; n++)
#pragma unroll
        for (int e = 0; e < 4; e++) o[n][e] = 0.f;
    float m0 = -INFINITY, m1 = -INFINITY, l0 = 0.f, l1 = 0.f;
    const float scale = 0.088388347648318447f;   // 1/sqrt(128)
    const int rq = wid * 16;

    const int nkt = 2 * qt + 2;     // FIX: cover keys [0, q0+128)
    for (int kt = 0; kt < nkt; kt++) {
        const int k0 = kt * 64;
        if (kt) __syncthreads();
        for (int f = tid; f < 1024; f += 256) {
            int row = f >> 4, seg = (f & 15) * 8;
            *(uint4*)&sKh[row * 136 + seg] = *(const uint4*)&Khg[(size_t)(k0 + row) * DD + seg];
            *(uint4*)&sKl[row * 136 + seg] = *(const uint4*)&Klg[(size_t)(k0 + row) * DD + seg];
        }
        for (int f = tid; f < 1024; f += 256) {
            int row = f >> 3, seg = (f & 7) * 8;
            *(uint4*)&sVh[row * 72 + seg] = *(const uint4*)&Vhg[(size_t)row * TT + k0 + seg];
            *(uint4*)&sVl[row * 72 + seg] = *(const uint4*)&Vlg[(size_t)row * TT + k0 + seg];
        }
        __syncthreads();

        // ---- S = Q K^T (bf16x3) ----
        float s[8][4];
#pragma unroll
        for (int j = 0; j < 8; j++)
#pragma unroll
            for (int e = 0; e < 4; e++) s[j][e] = 0.f;

#pragma unroll
        for (int ks = 0; ks < 8; ks++) {
            const int c = ks * 8 + kc;
            uint32_t ah[4], al[4];
            ah[0] = q32h[(rq + g) * 68 + c];
            ah[1] = q32h[(rq + g + 8) * 68 + c];
            ah[2] = q32h[(rq + g) * 68 + c + 4];
            ah[3] = q32h[(rq + g + 8) * 68 + c + 4];
            al[0] = q32l[(rq + g) * 68 + c];
            al[1] = q32l[(rq + g + 8) * 68 + c];
            al[2] = q32l[(rq + g) * 68 + c + 4];
            al[3] = q32l[(rq + g + 8) * 68 + c + 4];
#pragma unroll
            for (int j = 0; j < 8; j++) {
                int rn = (j * 8 + g) * 68 + c;
                uint32_t kb[2], kl2[2];
                kb[0]  = k32h[rn]; kb[1]  = k32h[rn + 4];
                kl2[0] = k32l[rn]; kl2[1] = k32l[rn + 4];
                mma_bf16(s[j], ah, kb);
                mma_bf16(s[j], ah, kl2);
                mma_bf16(s[j], al, kb);
            }
        }

        // scale + causal mask (only needed on the two diagonal tiles)
        const int row0 = q0 + rq + g;
        const int row1 = row0 + 8;
#pragma unroll
        for (int j = 0; j < 8; j++)
#pragma unroll
            for (int e = 0; e < 4; e++) s[j][e] *= scale;
        if (kt >= 2 * qt) {
#pragma unroll
            for (int j = 0; j < 8; j++) {
                int cb = k0 + j * 8 + kc * 2;
                if (cb     > row0) s[j][0] = -INFINITY;
                if (cb + 1 > row0) s[j][1] = -INFINITY;
                if (cb     > row1) s[j][2] = -INFINITY;
                if (cb + 1 > row1) s[j][3] = -INFINITY;
            }
        }

        // ---- online softmax (rows row0, row1 per thread; reduce over kc lanes) ----
        float mx0 = -INFINITY, mx1 = -INFINITY;
#pragma unroll
        for (int j = 0; j < 8; j++) {
            mx0 = fmaxf(mx0, fmaxf(s[j][0], s[j][1]));
            mx1 = fmaxf(mx1, fmaxf(s[j][2], s[j][3]));
        }
        mx0 = fmaxf(mx0, __shfl_xor_sync(0xffffffffu, mx0, 1));
        mx0 = fmaxf(mx0, __shfl_xor_sync(0xffffffffu, mx0, 2));
        mx1 = fmaxf(mx1, __shfl_xor_sync(0xffffffffu, mx1, 1));
        mx1 = fmaxf(mx1, __shfl_xor_sync(0xffffffffu, mx1, 2));
        float mn0 = fmaxf(m0, mx0), mn1 = fmaxf(m1, mx1);
        float r0 = __expf(m0 - mn0), r1 = __expf(m1 - mn1);
        float sum0 = 0.f, sum1 = 0.f;
#pragma unroll
        for (int j = 0; j < 8; j++) {
            s[j][0] = __expf(s[j][0] - mn0); sum0 += s[j][0];
            s[j][1] = __expf(s[j][1] - mn0); sum0 += s[j][1];
            s[j][2] = __expf(s[j][2] - mn1); sum1 += s[j][2];
            s[j][3] = __expf(s[j][3] - mn1); sum1 += s[j][3];
        }
        sum0 += __shfl_xor_sync(0xffffffffu, sum0, 1);
        sum0 += __shfl_xor_sync(0xffffffffu, sum0, 2);
        sum1 += __shfl_xor_sync(0xffffffffu, sum1, 1);
        sum1 += __shfl_xor_sync(0xffffffffu, sum1, 2);
        l0 = l0 * r0 + sum0;  m0 = mn0;
        l1 = l1 * r1 + sum1;  m1 = mn1;
#pragma unroll
        for (int n = 0; n < 16; n++) {
            o[n][0] *= r0; o[n][1] *= r0;
            o[n][2] *= r1; o[n][3] *= r1;
        }

        // ---- O += P V (bf16x3) ----
#pragma unroll
        for (int ks2 = 0; ks2 < 4; ks2++) {
            const int j0 = ks2 * 2, j1 = j0 + 1;
            uint32_t ph[4], pl[4];
            split2(s[j0][0], s[j0][1], ph[0], pl[0]);
            split2(s[j0][2], s[j0][3], ph[1], pl[1]);
            split2(s[j1][0], s[j1][1], ph[2], pl[2]);
            split2(s[j1][2], s[j1][3], ph[3], pl[3]);
            const int c = ks2 * 8 + kc;
#pragma unroll
            for (int nd = 0; nd < 16; nd++) {
                int rv = (nd * 8 + g) * 36 + c;
                uint32_t vb[2], vl2[2];
                vb[0]  = v32h[rv]; vb[1]  = v32h[rv + 4];
                vl2[0] = v32l[rv]; vl2[1] = v32l[rv + 4];
                mma_bf16(o[nd], ph, vb);
                mma_bf16(o[nd], ph, vl2);
                mma_bf16(o[nd], pl, vb);
            }
        }
    }

    // ---- epilogue: normalize + split -> g_ah / g_al [B,T,C] ----
    float i0 = 1.f / l0, i1 = 1.f / l1;
    const int b = bh >> 4, h = bh & 15;
    const int t0r = q0 + rq + g;
    __nv_bfloat16* ah0 = g_ah + ((size_t)(b * TT + t0r)) * CC + h * DD;
    __nv_bfloat16* al0 = g_al + ((size_t)(b * TT + t0r)) * CC + h * DD;
    __nv_bfloat16* ah1 = g_ah + ((size_t)(b * TT + t0r + 8)) * CC + h * DD;
    __nv_bfloat16* al1 = g_al + ((size_t)(b * TT + t0r + 8)) * CC + h * DD;
#pragma unroll
    for (int nd = 0; nd < 16; nd++) {
        int cc2 = nd * 8 + kc * 2;
        uint32_t hh, ll;
        split2(o[nd][0] * i0, o[nd][1] * i0, hh, ll);
        *(uint32_t*)&ah0[cc2] = hh;
        *(uint32_t*)&al0[cc2] = ll;
        split2(o[nd][2] * i1, o[nd][3] * i1, hh, ll);
        *(uint32_t*)&ah1[cc2] = hh;
        *(uint32_t*)&al1[cc2] = ll;
    }
}

// ============================================================
extern "C" void kernel_launch(void* const* d_in, const int* in_sizes, int n_in,
                              void* d_out, int out_size)
{
    const float* x  = (const float*)d_in[0];
    const float* Wq = (const float*)d_in[1];
    const float* Wk = (const float*)d_in[2];
    const float* Wv = (const float*)d_in[3];
    const float* Wo = (const float*)d_in[4];
    float* out = (float*)d_out;

    cudaFuncSetAttribute(attn_mma_kernel, cudaFuncAttributeMaxDynamicSharedMemorySize,
                         ATT_SMEM_BYTES);

    // 0) pre-split inputs/weights to bf16 hi/lo
    split_one<<<(MM * CC / 4 + 255) / 256, 256>>>(x, 0, MM * CC / 4);
    split_one<<<(CC * CC / 4 + 255) / 256, 256>>>(Wq, 1, CC * CC / 4);
    split_one<<<(CC * CC / 4 + 255) / 256, 256>>>(Wk, 2, CC * CC / 4);
    split_one<<<(CC * CC / 4 + 255) / 256, 256>>>(Wv, 3, CC * CC / 4);
    split_one<<<(CC * CC / 4 + 255) / 256, 256>>>(Wo, 4, CC * CC / 4);

    // 1) QKV projections (bf16x3 tensor cores) -> fp32 [B,H,T,D]
    mma_gemm_qkv<<<dim3(CC / 128, MM / 128, 3), 256>>>();

    // 2) RoPE + split q,k;  V transpose + split
    rope_split_kernel<<<dim3(TT, BH), 64>>>();
    vsplit_transpose<<<dim3(TT / 32, DD / 32, BH), 256>>>();

    // 3) tensor-core causal flash attention -> bf16 hi/lo rows
    attn_mma_kernel<<<dim3(TT / 128, BH), 256, ATT_SMEM_BYTES>>>();

    // 4) output projection (bf16x3 tensor cores) -> fp32 out
    mma_gemm_out<<<dim3(CC / 128, MM / 128), 256>>>(out);
}